// round 11
// baseline (speedup 1.0000x reference)
#include <cuda_runtime.h>
#include <cuda_bf16.h>
#include <cstdint>

#define THT 16
#define TWT 32
#define PH  (THT + 4)
#define PW  (TWT + 4)
#define TPE (PH * PW)     // 720 elements per staged plane
#define HH  512
#define WW  1024
#define CC  16
#define NTY 32
#define NTX 32
#define NBK (4 * NTY * NTX)

__device__ float        g_partials[NBK];
__device__ unsigned int g_count = 0;

__host__ __device__ constexpr uint32_t pk(int a, int b, int c, int d) {
    return (uint32_t)(a & 0xFF) | ((uint32_t)(b & 0xFF) << 8) |
           ((uint32_t)(c & 0xFF) << 16) | ((uint32_t)(d & 0xFF) << 24);
}

// Negated composed-sobel weights (bytes = cols dj=-2..1 of the 5x5 kernels).
// gxx*64 = vv(row) x hh(col); gyy*64 = hh(row) x vv(col); gxy*64 = dd(row) x dd(col)
// vv=[1,4,6,4,1] hh=[1,0,-2,0,1] dd=[-1,-2,0,2,1].
// Match flags are 0x80 (= -128 as s8) per matching byte, so dp4a(flags, -W)
// accumulates +128*W -> common positive scale 128, classifier-invariant.
#define NXX0 ((int)pk(-1, 0,  2, 0))
#define NXX1 ((int)pk(-4, 0,  8, 0))
#define NXX2 ((int)pk(-6, 0, 12, 0))
#define NXXC ((int)pk(-1,-4, -6,-4))
#define NYY2 ((int)pk( 2, 8, 12, 8))
#define NXY0 ((int)pk(-1,-2,  0, 2))
#define NXY1 ((int)pk(-2,-4,  0, 4))
#define NXY3 ((int)pk( 2, 4,  0,-4))
#define NXY4 ((int)pk( 1, 2,  0,-2))

__device__ __forceinline__ float bf_raw_to_f32(unsigned int u) {
    return __uint_as_float(u << 16);
}

// Exact per-byte equality flags for 4-bit payload bytes (labels 0..15):
// t = a ^ bcast(c) has bytes <= 15, so t + 0x7F per byte never carries.
// Result: 0x80 at equal bytes, 0x00 elsewhere. 3 SASS ops.
__device__ __forceinline__ int eqflags4(uint32_t a, uint32_t cm) {
    uint32_t t = a ^ cm;
    return (int)(~(t + 0x7F7F7F7Fu) & 0x80808080u);
}

// classifier (scale-invariant): t = s*gyy/(gxx+64eps), s = sign(-gxy+eps)
// dir = b2 + (tp & b1);  b1 = |t|>=tan(pi/10), b2 = |t|>=tan(3pi/10)
__device__ __forceinline__ int classify(int gxx, int gyy, int gxy) {
    int ai  = (gxy <= 0) ? gyy : -gyy;
    int ua  = abs(ai);
    int ub  = abs(gxx);
    int lhs = ua << 16;
    int nz  = (ai != 0);
    int b1  = (lhs >= 21294 * ub) & nz;           // tan(pi/10)*2^16
    int b2  = (lhs >= 90203 * ub) & nz;           // tan(3pi/10)*2^16
    int tp  = ((ai ^ gxx) >= 0);                  // sign(ai)==sign(gxx)
    return b2 + (tp & b1);                        // 0=H, 1=Diag, 2=V
}

__global__ void __launch_bounds__(256, 6)
steal_nms_kernel(const float* __restrict__ pred, const int* __restrict__ lab,
                 float* __restrict__ out)
{
    __shared__ __nv_bfloat16               sE[CC * TPE];  // exp(pred), bf16
    __shared__ __align__(16) unsigned char sL[TPE];       // label bytes
    __shared__ int4                        sLut[3];       // tap byte-offsets per dir
    __shared__ float                       wsum[8];
    __shared__ double                      sd[256];
    __shared__ unsigned int                s_flag;

    const int tid = threadIdx.x;
    const int b  = blockIdx.z;
    const int h0 = 2 + (int)blockIdx.y * THT;
    const int w0 = 2 + (int)blockIdx.x * TWT;

    if (tid < 3) {
        int4 v;
        if (tid == 0)      v = make_int4(-4, -2, 0, 2);                          // H
        else if (tid == 1) v = make_int4(2 - 4*PW, -2*PW, -2, 2*PW - 4);         // Diag
        else               v = make_int4(-4*PW, -2*PW, 0, 2*PW);                 // V
        sLut[tid] = v;
    }

    // ---- vectorized staging: 180 float4/int4 per plane, 16B-aligned ----
    if (tid < 180) {
        int row = tid / 9;                 // 0..19
        int c4  = tid - row * 9;           // 0..8
        int gh = h0 - 2 + row; if (gh > HH - 1) gh = HH - 1;
        int gw = w0 - 2 + c4 * 4; if (gw > WW - 4) gw = WW - 4;   // clamped lanes unused by valid pixels
        const size_t goff = (size_t)gh * WW + gw;
        const int j = row * PW + c4 * 4;

        // labels: int4 -> 4 packed bytes
        int4 L = *(const int4*)(lab + (size_t)b * (HH * WW) + goff);
        uint32_t pkl = (uint32_t)(L.x & 0xFF) | ((uint32_t)(L.y & 0xFF) << 8) |
                       ((uint32_t)(L.z & 0xFF) << 16) | ((uint32_t)L.w << 24);
        *(uint32_t*)(sL + j) = pkl;

        // exp planes: LDG.128 + 4 exp + 2 bf16x2 cvt + STS.64 per class
        const float* p = pred + (size_t)b * CC * (HH * WW) + goff;
        __nv_bfloat16* se = sE + j;
        #pragma unroll 4
        for (int c = 0; c < CC; ++c) {
            float4 v = *(const float4*)p;
            __nv_bfloat162 lo = __floats2bfloat162_rn(__expf(v.x), __expf(v.y));
            __nv_bfloat162 hi = __floats2bfloat162_rn(__expf(v.z), __expf(v.w));
            uint2 st;
            st.x = *(unsigned int*)&lo;
            st.y = *(unsigned int*)&hi;
            *(uint2*)se = st;
            p  += (size_t)(HH * WW);
            se += TPE;
        }
    }
    __syncthreads();

    float acc = 0.0f;
    {
        // Each thread owns two VERTICALLY ADJACENT pixels: rows lyy, lyy+1.
        // Their 5x5 windows share 4 row-words -> 6 row flag-words per class
        // instead of 10.
        const int lyy = (tid >> 5) << 1;   // 0,2,...,14
        const int lxx = tid & 31;
        const int h = h0 + lyy, w = w0 + lxx;
        const float fm0 = (h     < HH - 2 && w < WW - 2) ? 1.0f : 0.0f;
        const float fm1 = (h + 1 < HH - 2 && w < WW - 2) ? 1.0f : 0.0f;

        // ---- shared window build: 6 row words (cols -2..1), 6 col bytes ----
        uint32_t A[6], kb4, kb5, Cw0, Cw1;
        {
            int off0 = lyy * PW + lxx;
            int a = off0 & ~3;
            int m = off0 & 3;
            uint32_t sel = 0x3210u + (uint32_t)m * 0x1111u;
            uint32_t kb[6];
            #pragma unroll
            for (int r = 0; r < 6; ++r) {
                uint32_t u0 = *(const uint32_t*)(sL + a);
                uint32_t u1 = *(const uint32_t*)(sL + a + 4);
                A[r]  = __byte_perm(u0, u1, sel);
                kb[r] = (u1 >> (m * 8)) & 0xFFu;
                a += PW;
            }
            Cw0 = kb[0] | (kb[1] << 8) | (kb[2] << 16) | (kb[3] << 24);
            Cw1 = (Cw0 >> 8) | (kb[4] << 24);
            kb4 = kb[4];
            kb5 = kb[5];
        }

        const char* Eb0 = (const char*)sE + 2 * ((lyy + 2) * PW + (lxx + 2));

        #pragma unroll 4
        for (int c = 0; c < CC; ++c, Eb0 += 2 * TPE) {
            uint32_t cm = (uint32_t)c * 0x01010101u;
            int e0 = eqflags4(A[0], cm);
            int e1 = eqflags4(A[1], cm);
            int e2 = eqflags4(A[2], cm);
            int e3 = eqflags4(A[3], cm);
            int e4 = eqflags4(A[4], cm);
            int e5 = eqflags4(A[5], cm);
            int F0 = eqflags4(Cw0, cm);
            int F1 = eqflags4(Cw1, cm);
            int mk0 = (kb4 == (uint32_t)c) ? 128 : 0;
            int mk1 = (kb5 == (uint32_t)c) ? 128 : 0;

            // pixel 0: rows e0..e4, col F0, corner mk0
            int gxx0 = mk0, gyy0 = mk0, gxy0 = mk0;
            gxx0 = __dp4a(e0, NXX0, gxx0);
            gxx0 = __dp4a(e1, NXX1, gxx0);
            gxx0 = __dp4a(e2, NXX2, gxx0);
            gxx0 = __dp4a(e3, NXX1, gxx0);
            gxx0 = __dp4a(e4, NXX0, gxx0);
            gxx0 = __dp4a(F0, NXXC, gxx0);
            gyy0 = __dp4a(e0, NXXC, gyy0);
            gyy0 = __dp4a(e2, NYY2, gyy0);
            gyy0 = __dp4a(e4, NXXC, gyy0);
            gyy0 = __dp4a(F0, NXX0, gyy0);
            gxy0 = __dp4a(e0, NXY0, gxy0);
            gxy0 = __dp4a(e1, NXY1, gxy0);
            gxy0 = __dp4a(e3, NXY3, gxy0);
            gxy0 = __dp4a(e4, NXY4, gxy0);
            gxy0 = __dp4a(F0, NXY4, gxy0);

            // pixel 1: rows e1..e5, col F1, corner mk1
            int gxx1 = mk1, gyy1 = mk1, gxy1 = mk1;
            gxx1 = __dp4a(e1, NXX0, gxx1);
            gxx1 = __dp4a(e2, NXX1, gxx1);
            gxx1 = __dp4a(e3, NXX2, gxx1);
            gxx1 = __dp4a(e4, NXX1, gxx1);
            gxx1 = __dp4a(e5, NXX0, gxx1);
            gxx1 = __dp4a(F1, NXXC, gxx1);
            gyy1 = __dp4a(e1, NXXC, gyy1);
            gyy1 = __dp4a(e3, NYY2, gyy1);
            gyy1 = __dp4a(e5, NXXC, gyy1);
            gyy1 = __dp4a(F1, NXX0, gyy1);
            gxy1 = __dp4a(e1, NXY0, gxy1);
            gxy1 = __dp4a(e2, NXY1, gxy1);
            gxy1 = __dp4a(e4, NXY3, gxy1);
            gxy1 = __dp4a(e5, NXY4, gxy1);
            gxy1 = __dp4a(F1, NXY4, gxy1);

            int dir0 = classify(gxx0, gyy0, gxy0);
            int dir1 = classify(gxx1, gyy1, gxy1);

            {
                int4 o = sLut[dir0];
                unsigned int un = *(const unsigned short*)(Eb0);
                unsigned int u0 = *(const unsigned short*)(Eb0 + o.x);
                unsigned int u1 = *(const unsigned short*)(Eb0 + o.y);
                unsigned int u2 = *(const unsigned short*)(Eb0 + o.z);
                unsigned int u3 = *(const unsigned short*)(Eb0 + o.w);
                float den = bf_raw_to_f32(u0) + bf_raw_to_f32(u1) +
                            bf_raw_to_f32(u2) + bf_raw_to_f32(u3);
                acc = fmaf(fm0, __fdividef(bf_raw_to_f32(un), den), acc);
            }
            {
                const char* Eb1 = Eb0 + 2 * PW;
                int4 o = sLut[dir1];
                unsigned int un = *(const unsigned short*)(Eb1);
                unsigned int u0 = *(const unsigned short*)(Eb1 + o.x);
                unsigned int u1 = *(const unsigned short*)(Eb1 + o.y);
                unsigned int u2 = *(const unsigned short*)(Eb1 + o.z);
                unsigned int u3 = *(const unsigned short*)(Eb1 + o.w);
                float den = bf_raw_to_f32(u0) + bf_raw_to_f32(u1) +
                            bf_raw_to_f32(u2) + bf_raw_to_f32(u3);
                acc = fmaf(fm1, __fdividef(bf_raw_to_f32(un), den), acc);
            }
        }
    }

    // ---- block reduction -> per-block partial ----
    #pragma unroll
    for (int o = 16; o; o >>= 1) acc += __shfl_down_sync(0xFFFFFFFFu, acc, o);
    if ((tid & 31) == 0) wsum[tid >> 5] = acc;
    __syncthreads();
    if (tid < 8) {
        float v = wsum[tid];
        v += __shfl_down_sync(0xFFu, v, 4);
        v += __shfl_down_sync(0xFFu, v, 2);
        v += __shfl_down_sync(0xFFu, v, 1);
        if (tid == 0) {
            int bid = ((int)blockIdx.z * NTY + (int)blockIdx.y) * NTX + (int)blockIdx.x;
            g_partials[bid] = v;
            __threadfence();
            unsigned int t = atomicAdd(&g_count, 1u);
            s_flag = (t == NBK - 1) ? 1u : 0u;
        }
    }
    __syncthreads();

    // ---- last block: deterministic fixed-order final reduce in double ----
    if (s_flag) {
        __threadfence();
        double s = 0.0;
        for (int i = tid; i < NBK; i += 256) s += (double)g_partials[i];
        sd[tid] = s;
        __syncthreads();
        for (int st = 128; st; st >>= 1) {
            if (tid < st) sd[tid] += sd[tid + st];
            __syncthreads();
        }
        if (tid == 0) {
            out[0] = (float)sd[0];
            g_count = 0u;   // reset for next graph replay
        }
    }
}

extern "C" void kernel_launch(void* const* d_in, const int* in_sizes, int n_in,
                              void* d_out, int out_size)
{
    const float* pred = (const float*)d_in[0];
    const int*   lab  = (const int*)d_in[1];
    (void)in_sizes; (void)n_in; (void)out_size;

    dim3 grid(NTX, NTY, 4);
    steal_nms_kernel<<<grid, 256>>>(pred, lab, (float*)d_out);
}

// round 12
// speedup vs baseline: 1.3770x; 1.3770x over previous
#include <cuda_runtime.h>
#include <cuda_bf16.h>
#include <cstdint>

#define THT 16
#define TWT 32
#define PH  (THT + 4)
#define PW  (TWT + 4)
#define TPE (PH * PW)     // 720 elements per staged plane
#define HH  512
#define WW  1024
#define CC  16
#define NTY 32
#define NTX 32
#define NBK (4 * NTY * NTX)

__device__ float        g_partials[NBK];
__device__ unsigned int g_count = 0;

__host__ __device__ constexpr uint32_t pk(int a, int b, int c, int d) {
    return (uint32_t)(a & 0xFF) | ((uint32_t)(b & 0xFF) << 8) |
           ((uint32_t)(c & 0xFF) << 16) | ((uint32_t)(d & 0xFF) << 24);
}

// Negated composed-sobel weights (bytes = cols dj=-2..1 of the 5x5 kernels).
// gxx*64 = vv(row) x hh(col); gyy*64 = hh(row) x vv(col); gxy*64 = dd(row) x dd(col)
// vv=[1,4,6,4,1] hh=[1,0,-2,0,1] dd=[-1,-2,0,2,1].
// Match flags are 0x80 (= -128 as s8) per matching byte, so dp4a(flags, -W)
// accumulates +128*W -> common positive scale 128, classifier-invariant.
#define NXX0 ((int)pk(-1, 0,  2, 0))
#define NXX1 ((int)pk(-4, 0,  8, 0))
#define NXX2 ((int)pk(-6, 0, 12, 0))
#define NXXC ((int)pk(-1,-4, -6,-4))
#define NYY2 ((int)pk( 2, 8, 12, 8))
#define NXY0 ((int)pk(-1,-2,  0, 2))
#define NXY1 ((int)pk(-2,-4,  0, 4))
#define NXY3 ((int)pk( 2, 4,  0,-4))
#define NXY4 ((int)pk( 1, 2,  0,-2))

__device__ __forceinline__ float bf_raw_to_f32(unsigned int u) {
    return __uint_as_float(u << 16);
}

// Exact per-byte equality flags for 4-bit payload bytes (labels 0..15):
// t = a ^ bcast(c) has bytes <= 15, so t + 0x7F per byte never carries.
// Result: 0x80 at equal bytes, 0x00 elsewhere. 3 SASS ops.
__device__ __forceinline__ int eqflags4(uint32_t a, uint32_t cm) {
    uint32_t t = a ^ cm;
    return (int)(~(t + 0x7F7F7F7Fu) & 0x80808080u);
}

// classifier (scale-invariant): t = s*gyy/(gxx+64eps), s = sign(-gxy+eps)
// dir = b2 + (tp & b1);  b1 = |t|>=tan(pi/10), b2 = |t|>=tan(3pi/10)
__device__ __forceinline__ int classify(int gxx, int gyy, int gxy) {
    int ai  = (gxy <= 0) ? gyy : -gyy;
    int ua  = abs(ai);
    int ub  = abs(gxx);
    int lhs = ua << 16;
    int nz  = (ai != 0);
    int b1  = (lhs >= 21294 * ub) & nz;           // tan(pi/10)*2^16
    int b2  = (lhs >= 90203 * ub) & nz;           // tan(3pi/10)*2^16
    int tp  = ((ai ^ gxx) >= 0);                  // sign(ai)==sign(gxx)
    return b2 + (tp & b1);                        // 0=H, 1=Diag, 2=V
}

__global__ void __launch_bounds__(256, 6)
steal_nms_kernel(const float* __restrict__ pred, const int* __restrict__ lab,
                 float* __restrict__ out)
{
    __shared__ __nv_bfloat16               sE[CC * TPE];  // exp(pred), bf16
    __shared__ __align__(16) unsigned char sL[TPE];       // label bytes
    __shared__ int4                        sLut[3];       // tap byte-offsets per dir
    __shared__ float                       wsum[8];
    __shared__ double                      sd[256];
    __shared__ unsigned int                s_flag;

    const int tid = threadIdx.x;
    const int b  = blockIdx.z;
    const int h0 = 2 + (int)blockIdx.y * THT;
    const int w0 = 2 + (int)blockIdx.x * TWT;

    if (tid < 3) {
        int4 v;
        if (tid == 0)      v = make_int4(-4, -2, 0, 2);                          // H
        else if (tid == 1) v = make_int4(2 - 4*PW, -2*PW, -2, 2*PW - 4);         // Diag
        else               v = make_int4(-4*PW, -2*PW, 0, 2*PW);                 // V
        sLut[tid] = v;
    }

    // ---- vectorized staging: 180 float4/int4 per plane, 16B-aligned ----
    if (tid < 180) {
        int row = tid / 9;                 // 0..19
        int c4  = tid - row * 9;           // 0..8
        int gh = h0 - 2 + row; if (gh > HH - 1) gh = HH - 1;
        int gw = w0 - 2 + c4 * 4; if (gw > WW - 4) gw = WW - 4;   // clamped lanes unused by valid pixels
        const size_t goff = (size_t)gh * WW + gw;
        const int j = row * PW + c4 * 4;

        // labels: int4 -> 4 packed bytes
        int4 L = *(const int4*)(lab + (size_t)b * (HH * WW) + goff);
        uint32_t pkl = (uint32_t)(L.x & 0xFF) | ((uint32_t)(L.y & 0xFF) << 8) |
                       ((uint32_t)(L.z & 0xFF) << 16) | ((uint32_t)L.w << 24);
        *(uint32_t*)(sL + j) = pkl;

        // exp planes: LDG.128 + 4 exp + 2 bf16x2 cvt + STS.64 per class
        const float* p = pred + (size_t)b * CC * (HH * WW) + goff;
        __nv_bfloat16* se = sE + j;
        #pragma unroll 4
        for (int c = 0; c < CC; ++c) {
            float4 v = *(const float4*)p;
            __nv_bfloat162 lo = __floats2bfloat162_rn(__expf(v.x), __expf(v.y));
            __nv_bfloat162 hi = __floats2bfloat162_rn(__expf(v.z), __expf(v.w));
            uint2 st;
            st.x = *(unsigned int*)&lo;
            st.y = *(unsigned int*)&hi;
            *(uint2*)se = st;
            p  += (size_t)(HH * WW);
            se += TPE;
        }
    }
    __syncthreads();

    float acc = 0.0f;
    {
        // Each thread owns two VERTICALLY ADJACENT pixels: rows lyy, lyy+1.
        // Their 5x5 windows share 4 row-words -> 6 row flag-words per class
        // instead of 10. Pixels processed SERIALLY inside each class
        // iteration (unroll 1) to keep peak register pressure under the
        // occupancy-6 cap (R11 spilled with unroll 4).
        const int lyy = (tid >> 5) << 1;   // 0,2,...,14
        const int lxx = tid & 31;
        const int h = h0 + lyy, w = w0 + lxx;
        const float fm0 = (h     < HH - 2 && w < WW - 2) ? 1.0f : 0.0f;
        const float fm1 = (h + 1 < HH - 2 && w < WW - 2) ? 1.0f : 0.0f;

        // ---- shared window build: 6 row words (cols -2..1), 6 col bytes ----
        uint32_t A0w, A1w, A2w, A3w, A4w, A5w, kb4, kb5, Cw0, Cw1;
        {
            int off0 = lyy * PW + lxx;
            int a = off0 & ~3;
            int m = off0 & 3;
            uint32_t sel = 0x3210u + (uint32_t)m * 0x1111u;
            uint32_t Ar[6], kb[6];
            #pragma unroll
            for (int r = 0; r < 6; ++r) {
                uint32_t u0 = *(const uint32_t*)(sL + a);
                uint32_t u1 = *(const uint32_t*)(sL + a + 4);
                Ar[r] = __byte_perm(u0, u1, sel);
                kb[r] = (u1 >> (m * 8)) & 0xFFu;
                a += PW;
            }
            A0w = Ar[0]; A1w = Ar[1]; A2w = Ar[2];
            A3w = Ar[3]; A4w = Ar[4]; A5w = Ar[5];
            Cw0 = kb[0] | (kb[1] << 8) | (kb[2] << 16) | (kb[3] << 24);
            Cw1 = (Cw0 >> 8) | (kb[4] << 24);
            kb4 = kb[4];
            kb5 = kb[5];
        }

        const char* Eb0 = (const char*)sE + 2 * ((lyy + 2) * PW + (lxx + 2));

        #pragma unroll 1
        for (int c = 0; c < CC; ++c, Eb0 += 2 * TPE) {
            uint32_t cm = (uint32_t)c * 0x01010101u;
            int e0 = eqflags4(A0w, cm);
            int e1 = eqflags4(A1w, cm);
            int e2 = eqflags4(A2w, cm);
            int e3 = eqflags4(A3w, cm);
            int e4 = eqflags4(A4w, cm);
            int e5 = eqflags4(A5w, cm);

            // ---- pixel 0: rows e0..e4, col Cw0, corner kb4 ----
            {
                int F0  = eqflags4(Cw0, cm);
                int mk0 = (kb4 == (uint32_t)c) ? 128 : 0;
                int gxx = mk0, gyy = mk0, gxy = mk0;
                gxx = __dp4a(e0, NXX0, gxx);
                gxx = __dp4a(e1, NXX1, gxx);
                gxx = __dp4a(e2, NXX2, gxx);
                gxx = __dp4a(e3, NXX1, gxx);
                gxx = __dp4a(e4, NXX0, gxx);
                gxx = __dp4a(F0, NXXC, gxx);
                gyy = __dp4a(e0, NXXC, gyy);
                gyy = __dp4a(e2, NYY2, gyy);
                gyy = __dp4a(e4, NXXC, gyy);
                gyy = __dp4a(F0, NXX0, gyy);
                gxy = __dp4a(e0, NXY0, gxy);
                gxy = __dp4a(e1, NXY1, gxy);
                gxy = __dp4a(e3, NXY3, gxy);
                gxy = __dp4a(e4, NXY4, gxy);
                gxy = __dp4a(F0, NXY4, gxy);

                int4 o = sLut[classify(gxx, gyy, gxy)];
                unsigned int un = *(const unsigned short*)(Eb0);
                unsigned int u0 = *(const unsigned short*)(Eb0 + o.x);
                unsigned int u1 = *(const unsigned short*)(Eb0 + o.y);
                unsigned int u2 = *(const unsigned short*)(Eb0 + o.z);
                unsigned int u3 = *(const unsigned short*)(Eb0 + o.w);
                float den = bf_raw_to_f32(u0) + bf_raw_to_f32(u1) +
                            bf_raw_to_f32(u2) + bf_raw_to_f32(u3);
                acc = fmaf(fm0, __fdividef(bf_raw_to_f32(un), den), acc);
            }

            // ---- pixel 1: rows e1..e5, col Cw1, corner kb5 ----
            {
                int F1  = eqflags4(Cw1, cm);
                int mk1 = (kb5 == (uint32_t)c) ? 128 : 0;
                int gxx = mk1, gyy = mk1, gxy = mk1;
                gxx = __dp4a(e1, NXX0, gxx);
                gxx = __dp4a(e2, NXX1, gxx);
                gxx = __dp4a(e3, NXX2, gxx);
                gxx = __dp4a(e4, NXX1, gxx);
                gxx = __dp4a(e5, NXX0, gxx);
                gxx = __dp4a(F1, NXXC, gxx);
                gyy = __dp4a(e1, NXXC, gyy);
                gyy = __dp4a(e3, NYY2, gyy);
                gyy = __dp4a(e5, NXXC, gyy);
                gyy = __dp4a(F1, NXX0, gyy);
                gxy = __dp4a(e1, NXY0, gxy);
                gxy = __dp4a(e2, NXY1, gxy);
                gxy = __dp4a(e4, NXY3, gxy);
                gxy = __dp4a(e5, NXY4, gxy);
                gxy = __dp4a(F1, NXY4, gxy);

                const char* Eb1 = Eb0 + 2 * PW;
                int4 o = sLut[classify(gxx, gyy, gxy)];
                unsigned int un = *(const unsigned short*)(Eb1);
                unsigned int u0 = *(const unsigned short*)(Eb1 + o.x);
                unsigned int u1 = *(const unsigned short*)(Eb1 + o.y);
                unsigned int u2 = *(const unsigned short*)(Eb1 + o.z);
                unsigned int u3 = *(const unsigned short*)(Eb1 + o.w);
                float den = bf_raw_to_f32(u0) + bf_raw_to_f32(u1) +
                            bf_raw_to_f32(u2) + bf_raw_to_f32(u3);
                acc = fmaf(fm1, __fdividef(bf_raw_to_f32(un), den), acc);
            }
        }
    }

    // ---- block reduction -> per-block partial ----
    #pragma unroll
    for (int o = 16; o; o >>= 1) acc += __shfl_down_sync(0xFFFFFFFFu, acc, o);
    if ((tid & 31) == 0) wsum[tid >> 5] = acc;
    __syncthreads();
    if (tid < 8) {
        float v = wsum[tid];
        v += __shfl_down_sync(0xFFu, v, 4);
        v += __shfl_down_sync(0xFFu, v, 2);
        v += __shfl_down_sync(0xFFu, v, 1);
        if (tid == 0) {
            int bid = ((int)blockIdx.z * NTY + (int)blockIdx.y) * NTX + (int)blockIdx.x;
            g_partials[bid] = v;
            __threadfence();
            unsigned int t = atomicAdd(&g_count, 1u);
            s_flag = (t == NBK - 1) ? 1u : 0u;
        }
    }
    __syncthreads();

    // ---- last block: deterministic fixed-order final reduce in double ----
    if (s_flag) {
        __threadfence();
        double s = 0.0;
        for (int i = tid; i < NBK; i += 256) s += (double)g_partials[i];
        sd[tid] = s;
        __syncthreads();
        for (int st = 128; st; st >>= 1) {
            if (tid < st) sd[tid] += sd[tid + st];
            __syncthreads();
        }
        if (tid == 0) {
            out[0] = (float)sd[0];
            g_count = 0u;   // reset for next graph replay
        }
    }
}

extern "C" void kernel_launch(void* const* d_in, const int* in_sizes, int n_in,
                              void* d_out, int out_size)
{
    const float* pred = (const float*)d_in[0];
    const int*   lab  = (const int*)d_in[1];
    (void)in_sizes; (void)n_in; (void)out_size;

    dim3 grid(NTX, NTY, 4);
    steal_nms_kernel<<<grid, 256>>>(pred, lab, (float*)d_out);
}